// round 1
// baseline (speedup 1.0000x reference)
#include <cuda_runtime.h>
#include <cuda_bf16.h>
#include <math.h>

// Problem constants (fixed shapes)
#define BATCH 4
#define SEQ   4096
#define DMODEL 1024
#define DFF   4096
#define KSEL  1024           // active tokens per batch row
#define MROWS (BATCH * KSEL) // 4096 selected rows total

// -------- scratch (static device globals; no allocations allowed) --------
__device__ float g_scores[BATCH * SEQ];     // router scores
__device__ int   g_selidx[MROWS];           // selected token position within its batch row
__device__ float g_gate[MROWS];             // sigmoid(score) per selected row
__device__ float g_Asel[(size_t)MROWS * DMODEL]; // gathered tokens  [4096,1024]
__device__ float g_H[(size_t)MROWS * DFF];       // GELU(h)          [4096,4096]

// ---------------- router: scores[b,s] = x[b,s,:] . rw + rb ----------------
__global__ void router_kernel(const float* __restrict__ x,
                              const float* __restrict__ rw,
                              const float* __restrict__ rb) {
    int warp = (blockIdx.x * blockDim.x + threadIdx.x) >> 5;
    int lane = threadIdx.x & 31;
    if (warp >= BATCH * SEQ) return;
    const float4* xr = (const float4*)(x + (size_t)warp * DMODEL);
    const float4* w4 = (const float4*)rw;
    float acc = 0.f;
#pragma unroll 4
    for (int i = lane; i < DMODEL / 4; i += 32) {
        float4 a = xr[i], w = w4[i];
        acc += a.x * w.x + a.y * w.y + a.z * w.z + a.w * w.w;
    }
#pragma unroll
    for (int o = 16; o; o >>= 1) acc += __shfl_xor_sync(0xffffffffu, acc, o);
    if (lane == 0) g_scores[warp] = acc + rb[0];
}

// ------------- top-k per batch row: bitonic sort 4096 (key,idx) -------------
__global__ void topk_kernel() {
    __shared__ float skey[SEQ];
    __shared__ int   sidx[SEQ];
    int b = blockIdx.x, tid = threadIdx.x;
    for (int i = tid; i < SEQ; i += blockDim.x) {
        skey[i] = g_scores[b * SEQ + i];
        sidx[i] = i;
    }
    __syncthreads();
    for (int k = 2; k <= SEQ; k <<= 1) {
        for (int j = k >> 1; j > 0; j >>= 1) {
            for (int i = tid; i < SEQ; i += blockDim.x) {
                int ixj = i ^ j;
                if (ixj > i) {
                    bool desc = ((i & k) == 0);
                    float ka = skey[i], kb = skey[ixj];
                    bool swap = desc ? (ka < kb) : (ka > kb);
                    if (swap) {
                        skey[i] = kb; skey[ixj] = ka;
                        int t = sidx[i]; sidx[i] = sidx[ixj]; sidx[ixj] = t;
                    }
                }
            }
            __syncthreads();
        }
    }
    // first KSEL entries are the top-k (descending)
    if (tid < KSEL) {
        g_selidx[b * KSEL + tid] = sidx[tid];
        g_gate[b * KSEL + tid]   = 1.f / (1.f + expf(-skey[tid]));
    }
}

// -------------------- gather selected rows into g_Asel --------------------
__global__ void gather_kernel(const float* __restrict__ x) {
    int r = blockIdx.x;              // 0..MROWS-1
    int b = r >> 10;                 // /KSEL
    int pos = g_selidx[r];
    const float4* src = (const float4*)(x + ((size_t)b * SEQ + pos) * DMODEL);
    float4* dst = (float4*)(g_Asel + (size_t)r * DMODEL);
    dst[threadIdx.x] = src[threadIdx.x];   // 256 threads * float4 = 1024 floats
}

// ----------------------------- zero output -----------------------------
__global__ void zero_kernel(float4* __restrict__ out) {
    out[(size_t)blockIdx.x * blockDim.x + threadIdx.x] = make_float4(0.f, 0.f, 0.f, 0.f);
}

// ------------------------------- SGEMM ---------------------------------
// C = A[M,K] * W[K,N]; 128x128 tile, BK=8, 256 threads, 8x8/thread (split 4+4)
// EPI 0: A=g_Asel, C=g_H, epilogue = bias + exact GELU
// EPI 1: A=g_H,    C=out scattered, epilogue = bias, *gate, scatter row
template<int M, int N, int K, int EPI>
__global__ __launch_bounds__(256, 2)
void sgemm_kernel(const float* __restrict__ W,
                  const float* __restrict__ bias,
                  float* __restrict__ out) {
    __shared__ float As[8][128];
    __shared__ float Bs[8][128];

    const float* A = (EPI == 0) ? g_Asel : g_H;

    int tid = threadIdx.x;
    int tx = tid & 15, ty = tid >> 4;
    int bm = blockIdx.y * 128, bn = blockIdx.x * 128;

    int aRow = tid >> 1, aCol = (tid & 1) * 4;         // 128x8 A tile, float4/thread
    int bRow = tid >> 5, bCol = (tid & 31) * 4;        // 8x128 W tile, float4/thread

    const float* Aptr = A + (size_t)(bm + aRow) * K + aCol;
    const float* Bptr = W + (size_t)bRow * N + bn + bCol;

    float c[8][8];
#pragma unroll
    for (int i = 0; i < 8; i++)
#pragma unroll
        for (int j = 0; j < 8; j++) c[i][j] = 0.f;

    for (int k0 = 0; k0 < K; k0 += 8) {
        float4 av = *(const float4*)(Aptr + k0);
        float4 bv = *(const float4*)(Bptr + (size_t)k0 * N);
        As[aCol + 0][aRow] = av.x;
        As[aCol + 1][aRow] = av.y;
        As[aCol + 2][aRow] = av.z;
        As[aCol + 3][aRow] = av.w;
        *(float4*)&Bs[bRow][bCol] = bv;
        __syncthreads();
#pragma unroll
        for (int kk = 0; kk < 8; kk++) {
            float a[8], bb[8];
            *(float4*)(a + 0) = *(const float4*)&As[kk][ty * 4];
            *(float4*)(a + 4) = *(const float4*)&As[kk][64 + ty * 4];
            *(float4*)(bb + 0) = *(const float4*)&Bs[kk][tx * 4];
            *(float4*)(bb + 4) = *(const float4*)&Bs[kk][64 + tx * 4];
#pragma unroll
            for (int i = 0; i < 8; i++)
#pragma unroll
                for (int j = 0; j < 8; j++) c[i][j] += a[i] * bb[j];
        }
        __syncthreads();
    }

    // ------------------------- epilogue -------------------------
#pragma unroll
    for (int ih = 0; ih < 2; ih++) {
#pragma unroll
        for (int i = 0; i < 4; i++) {
            int row = bm + (ih ? 64 : 0) + ty * 4 + i;
            int ci = ih * 4 + i;
            float gateval = 1.f;
            size_t dstbase;
            if (EPI == 1) {
                int b = row >> 10;
                int pos = g_selidx[row];
                gateval = g_gate[row];
                dstbase = ((size_t)b * SEQ + pos) * DMODEL;
            } else {
                dstbase = (size_t)row * N;
            }
#pragma unroll
            for (int jh = 0; jh < 2; jh++) {
                int col = bn + (jh ? 64 : 0) + tx * 4;
                float4 v;
                v.x = c[ci][jh * 4 + 0] + bias[col + 0];
                v.y = c[ci][jh * 4 + 1] + bias[col + 1];
                v.z = c[ci][jh * 4 + 2] + bias[col + 2];
                v.w = c[ci][jh * 4 + 3] + bias[col + 3];
                if (EPI == 0) {
                    // exact GELU: 0.5*x*(1+erf(x/sqrt(2)))
                    v.x = 0.5f * v.x * (1.f + erff(v.x * 0.70710678118654752f));
                    v.y = 0.5f * v.y * (1.f + erff(v.y * 0.70710678118654752f));
                    v.z = 0.5f * v.z * (1.f + erff(v.z * 0.70710678118654752f));
                    v.w = 0.5f * v.w * (1.f + erff(v.w * 0.70710678118654752f));
                    *(float4*)&g_H[dstbase + col] = v;
                } else {
                    v.x *= gateval; v.y *= gateval; v.z *= gateval; v.w *= gateval;
                    *(float4*)&out[dstbase + col] = v;
                }
            }
        }
    }
}

// ------------------------------ launch ------------------------------
extern "C" void kernel_launch(void* const* d_in, const int* in_sizes, int n_in,
                              void* d_out, int out_size) {
    const float* x  = (const float*)d_in[0];
    const float* rw = (const float*)d_in[1];
    const float* rb = (const float*)d_in[2];
    const float* w1 = (const float*)d_in[3];
    const float* b1 = (const float*)d_in[4];
    const float* w2 = (const float*)d_in[5];
    const float* b2 = (const float*)d_in[6];
    float* out = (float*)d_out;

    // 1. router scores: 16384 tokens, 1 warp each
    router_kernel<<<(BATCH * SEQ) / 8, 256>>>(x, rw, rb);

    // 2. top-k select per batch row
    topk_kernel<<<BATCH, 1024>>>();

    // 3. gather selected rows
    gather_kernel<<<MROWS, 256>>>(x);

    // 4. GEMM1 + GELU -> g_H   [4096,1024]x[1024,4096]
    {
        dim3 grid(DFF / 128, MROWS / 128);
        sgemm_kernel<MROWS, DFF, DMODEL, 0><<<grid, 256>>>(w1, b1, nullptr);
    }

    // 5. zero the output (64 MB)
    zero_kernel<<<(BATCH * SEQ * DMODEL / 4) / 256, 256>>>((float4*)out);

    // 6. GEMM2 + gate + scatter  [4096,4096]x[4096,1024]
    {
        dim3 grid(DMODEL / 128, MROWS / 128);
        sgemm_kernel<MROWS, DMODEL, DFF, 1><<<grid, 256>>>(w2, b2, out);
    }
}

// round 3
// speedup vs baseline: 2.3346x; 2.3346x over previous
#include <cuda_runtime.h>
#include <cuda_bf16.h>
#include <math.h>
#include <stdint.h>

#define BATCH  4
#define SEQ    4096
#define DMODEL 1024
#define DFF    4096
#define KSEL   1024
#define MROWS  4096

// ------------------------- device scratch (no allocs) -------------------------
__device__ float g_scores[BATCH * SEQ];
__device__ int   g_selidx[MROWS];
__device__ float g_gate[MROWS];
__device__ __nv_bfloat16 g_Ahi[(size_t)MROWS * DMODEL];
__device__ __nv_bfloat16 g_Alo[(size_t)MROWS * DMODEL];
__device__ __nv_bfloat16 g_Hhi[(size_t)MROWS * DFF];
__device__ __nv_bfloat16 g_Hlo[(size_t)MROWS * DFF];
__device__ __nv_bfloat16 g_W1hi[(size_t)DFF * DMODEL];   // [N=4096][K=1024] (W1^T)
__device__ __nv_bfloat16 g_W1lo[(size_t)DFF * DMODEL];
__device__ __nv_bfloat16 g_W2hi[(size_t)DMODEL * DFF];   // [N=1024][K=4096] (W2^T)
__device__ __nv_bfloat16 g_W2lo[(size_t)DMODEL * DFF];

// ------------------------------ helpers ------------------------------
__device__ __forceinline__ uint32_t smem_u32(const void* p) {
    uint32_t a;
    asm("{ .reg .u64 t; cvta.to.shared.u64 t, %1; cvt.u32.u64 %0, t; }"
        : "=r"(a) : "l"(p));
    return a;
}

__device__ __forceinline__ void ldsm4(uint32_t* r, uint32_t addr) {
    asm volatile("ldmatrix.sync.aligned.m8n8.x4.shared.b16 {%0,%1,%2,%3}, [%4];"
                 : "=r"(r[0]), "=r"(r[1]), "=r"(r[2]), "=r"(r[3]) : "r"(addr));
}

__device__ __forceinline__ void mma16816(float* c, const uint32_t* a, const uint32_t* b) {
    asm volatile(
        "mma.sync.aligned.m16n8k16.row.col.f32.bf16.bf16.f32 "
        "{%0,%1,%2,%3}, {%4,%5,%6,%7}, {%8,%9}, {%0,%1,%2,%3};"
        : "+f"(c[0]), "+f"(c[1]), "+f"(c[2]), "+f"(c[3])
        : "r"(a[0]), "r"(a[1]), "r"(a[2]), "r"(a[3]), "r"(b[0]), "r"(b[1]));
}

__device__ __forceinline__ void cp16(uint32_t dst, const void* src) {
    asm volatile("cp.async.cg.shared.global [%0], [%1], 16;" :: "r"(dst), "l"(src));
}

// swizzled byte offset within a 128-row x 64B tile
__device__ __forceinline__ uint32_t swz(int row, int u) {
    return (uint32_t)(row * 64 + ((u ^ ((row >> 1) & 3)) << 4));
}

// ------------------------------ router ------------------------------
__global__ void router_kernel(const float* __restrict__ x,
                              const float* __restrict__ rw,
                              const float* __restrict__ rb) {
    int warp = (blockIdx.x * blockDim.x + threadIdx.x) >> 5;
    int lane = threadIdx.x & 31;
    if (warp >= BATCH * SEQ) return;
    const float4* xr = (const float4*)(x + (size_t)warp * DMODEL);
    const float4* w4 = (const float4*)rw;
    float acc = 0.f;
#pragma unroll 4
    for (int i = lane; i < DMODEL / 4; i += 32) {
        float4 a = xr[i], w = w4[i];
        acc += a.x * w.x + a.y * w.y + a.z * w.z + a.w * w.w;
    }
#pragma unroll
    for (int o = 16; o; o >>= 1) acc += __shfl_xor_sync(0xffffffffu, acc, o);
    if (lane == 0) g_scores[warp] = acc + rb[0];
}

// ------------------------------ top-k ------------------------------
__global__ void topk_kernel() {
    __shared__ float skey[SEQ];
    __shared__ int   sidx[SEQ];
    int b = blockIdx.x, tid = threadIdx.x;
    for (int i = tid; i < SEQ; i += blockDim.x) {
        skey[i] = g_scores[b * SEQ + i];
        sidx[i] = i;
    }
    __syncthreads();
    for (int k = 2; k <= SEQ; k <<= 1) {
        for (int j = k >> 1; j > 0; j >>= 1) {
            for (int i = tid; i < SEQ; i += blockDim.x) {
                int ixj = i ^ j;
                if (ixj > i) {
                    bool desc = ((i & k) == 0);
                    float ka = skey[i], kb = skey[ixj];
                    bool sw = desc ? (ka < kb) : (ka > kb);
                    if (sw) {
                        skey[i] = kb; skey[ixj] = ka;
                        int t = sidx[i]; sidx[i] = sidx[ixj]; sidx[ixj] = t;
                    }
                }
            }
            __syncthreads();
        }
    }
    if (tid < KSEL) {
        g_selidx[b * KSEL + tid] = sidx[tid];
        g_gate[b * KSEL + tid]   = 1.f / (1.f + expf(-skey[tid]));
    }
}

// -------------------- gather selected rows -> bf16 hi/lo --------------------
__global__ void gather_convert(const float* __restrict__ x) {
    int r = blockIdx.x;
    int b = r >> 10;
    int pos = g_selidx[r];
    const float4* src = (const float4*)(x + ((size_t)b * SEQ + pos) * DMODEL);
    float4 v = src[threadIdx.x];
    float a[4] = {v.x, v.y, v.z, v.w};
    __align__(8) __nv_bfloat16 h[4], l[4];
#pragma unroll
    for (int k = 0; k < 4; ++k) {
        h[k] = __float2bfloat16(a[k]);
        l[k] = __float2bfloat16(a[k] - __bfloat162float(h[k]));
    }
    size_t o = (size_t)r * DMODEL + 4 * threadIdx.x;
    *(uint2*)&g_Ahi[o] = *(uint2*)h;
    *(uint2*)&g_Alo[o] = *(uint2*)l;
}

// -------------------- transpose + split weights --------------------
template<int W>
__global__ void transpose_split(const float* __restrict__ src) {
    constexpr int R = (W == 0) ? DMODEL : DFF;
    constexpr int C = (W == 0) ? DFF : DMODEL;
    __nv_bfloat16* Ohi = (W == 0) ? g_W1hi : g_W2hi;
    __nv_bfloat16* Olo = (W == 0) ? g_W1lo : g_W2lo;
    __shared__ float t[32][33];
    int c0 = blockIdx.x * 32, r0 = blockIdx.y * 32;
    int tx = threadIdx.x, ty = threadIdx.y;
#pragma unroll
    for (int j = 0; j < 32; j += 8)
        t[ty + j][tx] = src[(size_t)(r0 + ty + j) * C + c0 + tx];
    __syncthreads();
#pragma unroll
    for (int j = 0; j < 32; j += 8) {
        float v = t[tx][ty + j];
        __nv_bfloat16 h = __float2bfloat16(v);
        size_t o = (size_t)(c0 + ty + j) * R + r0 + tx;
        Ohi[o] = h;
        Olo[o] = __float2bfloat16(v - __bfloat162float(h));
    }
}

// ------------------------------ zero output ------------------------------
__global__ void zero_kernel(float4* __restrict__ out) {
    out[(size_t)blockIdx.x * blockDim.x + threadIdx.x] = make_float4(0.f, 0.f, 0.f, 0.f);
}

// --------------------------- HMMA GEMM ---------------------------
// C[128x128 tile] = A[M,K] * B^T (B stored [N][K]), bf16x3, fp32 accum.
// 8 warps as 2(M) x 4(N); warp tile 64x32; K-chunk 32; 4-stage cp.async.
// Stage layout (32KB): Ahi @0, Alo @8K, Bhi @16K, Blo @24K; rows of 64B, swizzled.
#define STAGES 4
#define STAGE_BYTES 32768
#define GEMM_SMEM (STAGES * STAGE_BYTES)

template<int KDIM, int EPI>
__global__ __launch_bounds__(256, 1)
void hmma_gemm(const float* __restrict__ bias, float* __restrict__ out) {
    extern __shared__ __align__(128) char smem[];
    const int tid = threadIdx.x, l = tid & 31, wid = tid >> 5;
    const int wm = wid >> 2, wn = wid & 3;
    const int bm = blockIdx.y * 128, bn = blockIdx.x * 128;
    const uint32_t sb = smem_u32(smem);
    constexpr int NC = KDIM / 32;

    const __nv_bfloat16 *Ahi, *Alo, *Bhi, *Blo;
    if (EPI == 0) { Ahi = g_Ahi; Alo = g_Alo; Bhi = g_W1hi; Blo = g_W1lo; }
    else          { Ahi = g_Hhi; Alo = g_Hlo; Bhi = g_W2hi; Blo = g_W2lo; }

    float acc[4][4][4];
#pragma unroll
    for (int i = 0; i < 4; ++i)
#pragma unroll
        for (int j = 0; j < 4; ++j)
#pragma unroll
            for (int k = 0; k < 4; ++k) acc[i][j][k] = 0.f;

    // per-thread cp.async assignment: j-th slice, sec = j>>1 (0 Ahi,1 Alo,2 Bhi,3 Blo)
    const int lrow = (tid + ((0) & 1) * 256) >> 2; // recomputed in loop
    (void)lrow;

    auto load_stage = [&](int ck) {
        uint32_t sbase = sb + (ck & (STAGES - 1)) * STAGE_BYTES;
#pragma unroll
        for (int j = 0; j < 8; ++j) {
            const int sec = j >> 1;
            int w = tid + (j & 1) * 256;
            int row = w >> 2, u = w & 3;
            uint32_t dst = sbase + sec * 8192 + swz(row, u);
            const __nv_bfloat16* g;
            int grow;
            if (sec == 0)      { g = Ahi; grow = bm + row; }
            else if (sec == 1) { g = Alo; grow = bm + row; }
            else if (sec == 2) { g = Bhi; grow = bn + row; }
            else               { g = Blo; grow = bn + row; }
            cp16(dst, g + (size_t)grow * KDIM + ck * 32 + u * 8);
        }
        asm volatile("cp.async.commit_group;" ::: "memory");
    };

    // prologue
#pragma unroll
    for (int s = 0; s < STAGES - 1; ++s) load_stage(s);

    for (int c = 0; c < NC; ++c) {
        asm volatile("cp.async.wait_group %0;" :: "n"(STAGES - 2) : "memory");
        __syncthreads();
        if (c + STAGES - 1 < NC) load_stage(c + STAGES - 1);
        uint32_t sbase = sb + (c & (STAGES - 1)) * STAGE_BYTES;
#pragma unroll
        for (int s = 0; s < 2; ++s) {
            uint32_t ah[4][4], al[4][4], bh[4][2], bl[4][2];
#pragma unroll
            for (int mt = 0; mt < 4; ++mt) {
                int row = wm * 64 + mt * 16 + (l & 15);
                int u = s * 2 + (l >> 4);
                uint32_t ad = sbase + swz(row, u);
                ldsm4(ah[mt], ad);
                ldsm4(al[mt], ad + 8192);
            }
#pragma unroll
            for (int p = 0; p < 2; ++p) {
                int row = wn * 32 + p * 16 + ((l >> 4) << 3) + (l & 7);
                int u = s * 2 + ((l >> 3) & 1);
                uint32_t bd = sbase + 16384 + swz(row, u);
                uint32_t rh[4], rl[4];
                ldsm4(rh, bd);
                ldsm4(rl, bd + 8192);
                bh[p * 2][0] = rh[0]; bh[p * 2][1] = rh[1];
                bh[p * 2 + 1][0] = rh[2]; bh[p * 2 + 1][1] = rh[3];
                bl[p * 2][0] = rl[0]; bl[p * 2][1] = rl[1];
                bl[p * 2 + 1][0] = rl[2]; bl[p * 2 + 1][1] = rl[3];
            }
#pragma unroll
            for (int mt = 0; mt < 4; ++mt)
#pragma unroll
                for (int nt = 0; nt < 4; ++nt) {
                    mma16816(acc[mt][nt], ah[mt], bh[nt]);
                    mma16816(acc[mt][nt], ah[mt], bl[nt]);
                    mma16816(acc[mt][nt], al[mt], bh[nt]);
                }
        }
    }

    // ------------------------- epilogue -------------------------
    const int r0base = bm + wm * 64;
    const int c0base = bn + wn * 32;
#pragma unroll
    for (int mt = 0; mt < 4; ++mt) {
#pragma unroll
        for (int half = 0; half < 2; ++half) {
            int row = r0base + mt * 16 + (l >> 2) + half * 8;
            if (EPI == 0) {
#pragma unroll
                for (int nt = 0; nt < 4; ++nt) {
                    int col = c0base + nt * 8 + (l & 3) * 2;
                    float v0 = acc[mt][nt][half * 2 + 0] + __ldg(&bias[col]);
                    float v1 = acc[mt][nt][half * 2 + 1] + __ldg(&bias[col + 1]);
                    v0 = 0.5f * v0 * (1.f + erff(v0 * 0.70710678118654752f));
                    v1 = 0.5f * v1 * (1.f + erff(v1 * 0.70710678118654752f));
                    __nv_bfloat16 h0 = __float2bfloat16(v0);
                    __nv_bfloat16 h1 = __float2bfloat16(v1);
                    __nv_bfloat16 l0 = __float2bfloat16(v0 - __bfloat162float(h0));
                    __nv_bfloat16 l1 = __float2bfloat16(v1 - __bfloat162float(h1));
                    uint32_t hp = ((uint32_t)__bfloat16_as_ushort(h1) << 16) |
                                  __bfloat16_as_ushort(h0);
                    uint32_t lp = ((uint32_t)__bfloat16_as_ushort(l1) << 16) |
                                  __bfloat16_as_ushort(l0);
                    size_t o = (size_t)row * DFF + col;
                    *(uint32_t*)&g_Hhi[o] = hp;
                    *(uint32_t*)&g_Hlo[o] = lp;
                }
            } else {
                int b = row >> 10;
                int pos = g_selidx[row];
                float gt = g_gate[row];
                size_t o = ((size_t)b * SEQ + pos) * DMODEL;
#pragma unroll
                for (int nt = 0; nt < 4; ++nt) {
                    int col = c0base + nt * 8 + (l & 3) * 2;
                    float2 w;
                    w.x = (acc[mt][nt][half * 2 + 0] + __ldg(&bias[col])) * gt;
                    w.y = (acc[mt][nt][half * 2 + 1] + __ldg(&bias[col + 1])) * gt;
                    *(float2*)&out[o + col] = w;
                }
            }
        }
    }
}

// ------------------------------ launch ------------------------------
extern "C" void kernel_launch(void* const* d_in, const int* in_sizes, int n_in,
                              void* d_out, int out_size) {
    const float* x  = (const float*)d_in[0];
    const float* rw = (const float*)d_in[1];
    const float* rb = (const float*)d_in[2];
    const float* w1 = (const float*)d_in[3];
    const float* b1 = (const float*)d_in[4];
    const float* w2 = (const float*)d_in[5];
    const float* b2 = (const float*)d_in[6];
    float* out = (float*)d_out;

    static bool attr_done = false;
    cudaFuncSetAttribute(hmma_gemm<DMODEL, 0>, cudaFuncAttributeMaxDynamicSharedMemorySize, GEMM_SMEM);
    cudaFuncSetAttribute(hmma_gemm<DFF, 1>,    cudaFuncAttributeMaxDynamicSharedMemorySize, GEMM_SMEM);
    (void)attr_done;

    router_kernel<<<(BATCH * SEQ) / 8, 256>>>(x, rw, rb);
    topk_kernel<<<BATCH, 1024>>>();
    gather_convert<<<MROWS, 256>>>(x);
    transpose_split<0><<<dim3(DFF / 32, DMODEL / 32), dim3(32, 8)>>>(w1);
    transpose_split<1><<<dim3(DMODEL / 32, DFF / 32), dim3(32, 8)>>>(w2);

    // GEMM1 + GELU -> H (bf16 hi/lo)
    hmma_gemm<DMODEL, 0><<<dim3(DFF / 128, MROWS / 128), 256, GEMM_SMEM>>>(b1, nullptr);

    zero_kernel<<<(BATCH * SEQ * DMODEL / 4) / 256, 256>>>((float4*)out);

    // GEMM2 + gate + scatter
    hmma_gemm<DFF, 1><<<dim3(DMODEL / 128, MROWS / 128), 256, GEMM_SMEM>>>(b2, out);
}

// round 4
// speedup vs baseline: 3.0863x; 1.3220x over previous
#include <cuda_runtime.h>
#include <cuda_fp16.h>
#include <math.h>
#include <stdint.h>

#define BATCH  4
#define SEQ    4096
#define DMODEL 1024
#define DFF    4096
#define KSEL   1024
#define MROWS  4096

// ------------------------- device scratch (no allocs) -------------------------
__device__ float g_scores[BATCH * SEQ];
__device__ int   g_selidx[MROWS];
__device__ float g_gate[MROWS];
__device__ __half g_A[(size_t)MROWS * DMODEL];          // gathered tokens, fp16
__device__ __half g_H[(size_t)MROWS * DFF];             // GELU(h), fp16
__device__ __half g_W1hi[(size_t)DFF * DMODEL];         // [N][K] = W1^T hi
__device__ __half g_W1lo[(size_t)DFF * DMODEL];         // W1^T lo
__device__ __half g_W2hi[(size_t)DMODEL * DFF];         // W2^T hi
__device__ __half g_W2lo[(size_t)DMODEL * DFF];         // W2^T lo

// ------------------------------ helpers ------------------------------
__device__ __forceinline__ uint32_t smem_u32(const void* p) {
    uint32_t a;
    asm("{ .reg .u64 t; cvta.to.shared.u64 t, %1; cvt.u32.u64 %0, t; }"
        : "=r"(a) : "l"(p));
    return a;
}

__device__ __forceinline__ void ldsm4(uint32_t* r, uint32_t addr) {
    asm volatile("ldmatrix.sync.aligned.m8n8.x4.shared.b16 {%0,%1,%2,%3}, [%4];"
                 : "=r"(r[0]), "=r"(r[1]), "=r"(r[2]), "=r"(r[3]) : "r"(addr));
}

__device__ __forceinline__ void mma16816(float* c, const uint32_t* a, const uint32_t* b) {
    asm volatile(
        "mma.sync.aligned.m16n8k16.row.col.f32.f16.f16.f32 "
        "{%0,%1,%2,%3}, {%4,%5,%6,%7}, {%8,%9}, {%0,%1,%2,%3};"
        : "+f"(c[0]), "+f"(c[1]), "+f"(c[2]), "+f"(c[3])
        : "r"(a[0]), "r"(a[1]), "r"(a[2]), "r"(a[3]), "r"(b[0]), "r"(b[1]));
}

__device__ __forceinline__ void cp16(uint32_t dst, const void* src) {
    asm volatile("cp.async.cg.shared.global [%0], [%1], 16;" :: "r"(dst), "l"(src));
}

// swizzled byte offset within a 128-row x 64B tile
__device__ __forceinline__ uint32_t swz(int row, int u) {
    return (uint32_t)(row * 64 + ((u ^ ((row >> 1) & 3)) << 4));
}

// ------------------------------ router ------------------------------
__global__ void router_kernel(const float* __restrict__ x,
                              const float* __restrict__ rw,
                              const float* __restrict__ rb) {
    int warp = (blockIdx.x * blockDim.x + threadIdx.x) >> 5;
    int lane = threadIdx.x & 31;
    if (warp >= BATCH * SEQ) return;
    const float4* xr = (const float4*)(x + (size_t)warp * DMODEL);
    const float4* w4 = (const float4*)rw;
    float acc = 0.f;
#pragma unroll 4
    for (int i = lane; i < DMODEL / 4; i += 32) {
        float4 a = xr[i], w = w4[i];
        acc += a.x * w.x + a.y * w.y + a.z * w.z + a.w * w.w;
    }
#pragma unroll
    for (int o = 16; o; o >>= 1) acc += __shfl_xor_sync(0xffffffffu, acc, o);
    if (lane == 0) g_scores[warp] = acc + rb[0];
}

// ------------------------------ top-k ------------------------------
__global__ void topk_kernel() {
    __shared__ float skey[SEQ];
    __shared__ int   sidx[SEQ];
    int b = blockIdx.x, tid = threadIdx.x;
    for (int i = tid; i < SEQ; i += blockDim.x) {
        skey[i] = g_scores[b * SEQ + i];
        sidx[i] = i;
    }
    __syncthreads();
    for (int k = 2; k <= SEQ; k <<= 1) {
        for (int j = k >> 1; j > 0; j >>= 1) {
            for (int i = tid; i < SEQ; i += blockDim.x) {
                int ixj = i ^ j;
                if (ixj > i) {
                    bool desc = ((i & k) == 0);
                    float ka = skey[i], kb = skey[ixj];
                    bool sw = desc ? (ka < kb) : (ka > kb);
                    if (sw) {
                        skey[i] = kb; skey[ixj] = ka;
                        int t = sidx[i]; sidx[i] = sidx[ixj]; sidx[ixj] = t;
                    }
                }
            }
            __syncthreads();
        }
    }
    if (tid < KSEL) {
        g_selidx[b * KSEL + tid] = sidx[tid];
        g_gate[b * KSEL + tid]   = 1.f / (1.f + expf(-skey[tid]));
    }
}

// -------------------- gather selected rows -> fp16 --------------------
__global__ void gather_convert(const float* __restrict__ x) {
    int r = blockIdx.x;
    int b = r >> 10;
    int pos = g_selidx[r];
    const float4* src = (const float4*)(x + ((size_t)b * SEQ + pos) * DMODEL);
    float4 v = src[threadIdx.x];
    __align__(8) __half h[4];
    h[0] = __float2half(v.x); h[1] = __float2half(v.y);
    h[2] = __float2half(v.z); h[3] = __float2half(v.w);
    size_t o = (size_t)r * DMODEL + 4 * threadIdx.x;
    *(uint2*)&g_A[o] = *(uint2*)h;
}

// -------------------- transpose + split weights (fp16 hi/lo) --------------------
template<int W>
__global__ void transpose_split(const float* __restrict__ src) {
    constexpr int R = (W == 0) ? DMODEL : DFF;
    constexpr int C = (W == 0) ? DFF : DMODEL;
    __half* Ohi = (W == 0) ? g_W1hi : g_W2hi;
    __half* Olo = (W == 0) ? g_W1lo : g_W2lo;
    __shared__ float t[32][33];
    int c0 = blockIdx.x * 32, r0 = blockIdx.y * 32;
    int tx = threadIdx.x, ty = threadIdx.y;
#pragma unroll
    for (int j = 0; j < 32; j += 8)
        t[ty + j][tx] = src[(size_t)(r0 + ty + j) * C + c0 + tx];
    __syncthreads();
#pragma unroll
    for (int j = 0; j < 32; j += 8) {
        float v = t[tx][ty + j];
        __half h = __float2half(v);
        size_t o = (size_t)(c0 + ty + j) * R + r0 + tx;
        Ohi[o] = h;
        Olo[o] = __float2half(v - __half2float(h));
    }
}

// ------------------------------ zero output ------------------------------
__global__ void zero_kernel(float4* __restrict__ out) {
    out[(size_t)blockIdx.x * blockDim.x + threadIdx.x] = make_float4(0.f, 0.f, 0.f, 0.f);
}

// --------------------------- HMMA GEMM ---------------------------
// C[128x128 tile] = A[M,K] * (Bhi+Blo)^T; A fp16 single, B fp16 hi/lo; fp32 accum.
// 8 warps as 2(M) x 4(N); warp tile 64x32; K-chunk 32; 4-stage cp.async.
// Stage (24KB): A @0, Bhi @8K, Blo @16K; rows of 64B, swizzled.
#define STAGES 4
#define STAGE_BYTES 24576
#define GEMM_SMEM (STAGES * STAGE_BYTES)

template<int KDIM, int EPI>
__global__ __launch_bounds__(256, 1)
void hmma_gemm(const float* __restrict__ bias, float* __restrict__ out) {
    extern __shared__ __align__(128) char smem[];
    const int tid = threadIdx.x, l = tid & 31, wid = tid >> 5;
    const int wm = wid >> 2, wn = wid & 3;
    const int bm = blockIdx.y * 128, bn = blockIdx.x * 128;
    const uint32_t sb = smem_u32(smem);
    constexpr int NC = KDIM / 32;

    const __half *A, *Bhi, *Blo;
    if (EPI == 0) { A = g_A; Bhi = g_W1hi; Blo = g_W1lo; }
    else          { A = g_H; Bhi = g_W2hi; Blo = g_W2lo; }

    float acc[4][4][4];
#pragma unroll
    for (int i = 0; i < 4; ++i)
#pragma unroll
        for (int j = 0; j < 4; ++j)
#pragma unroll
            for (int k = 0; k < 4; ++k) acc[i][j][k] = 0.f;

    auto load_stage = [&](int ck) {
        uint32_t sbase = sb + (ck & (STAGES - 1)) * STAGE_BYTES;
#pragma unroll
        for (int j = 0; j < 6; ++j) {
            const int sec = j >> 1;           // 0=A, 1=Bhi, 2=Blo
            int w = tid + (j & 1) * 256;
            int row = w >> 2, u = w & 3;
            uint32_t dst = sbase + sec * 8192 + swz(row, u);
            const __half* g;
            int grow;
            if (sec == 0)      { g = A;   grow = bm + row; }
            else if (sec == 1) { g = Bhi; grow = bn + row; }
            else               { g = Blo; grow = bn + row; }
            cp16(dst, g + (size_t)grow * KDIM + ck * 32 + u * 8);
        }
        asm volatile("cp.async.commit_group;" ::: "memory");
    };

    // prologue
#pragma unroll
    for (int s = 0; s < STAGES - 1; ++s) load_stage(s);

    for (int c = 0; c < NC; ++c) {
        asm volatile("cp.async.wait_group %0;" :: "n"(STAGES - 2) : "memory");
        __syncthreads();
        if (c + STAGES - 1 < NC) load_stage(c + STAGES - 1);
        uint32_t sbase = sb + (c & (STAGES - 1)) * STAGE_BYTES;
#pragma unroll
        for (int s = 0; s < 2; ++s) {
            uint32_t ah[4][4], bh[4][2], bl[4][2];
#pragma unroll
            for (int mt = 0; mt < 4; ++mt) {
                int row = wm * 64 + mt * 16 + (l & 15);
                int u = s * 2 + (l >> 4);
                ldsm4(ah[mt], sbase + swz(row, u));
            }
#pragma unroll
            for (int p = 0; p < 2; ++p) {
                int row = wn * 32 + p * 16 + ((l >> 4) << 3) + (l & 7);
                int u = s * 2 + ((l >> 3) & 1);
                uint32_t bd = sbase + 8192 + swz(row, u);
                uint32_t rh[4], rl[4];
                ldsm4(rh, bd);
                ldsm4(rl, bd + 8192);
                bh[p * 2][0] = rh[0]; bh[p * 2][1] = rh[1];
                bh[p * 2 + 1][0] = rh[2]; bh[p * 2 + 1][1] = rh[3];
                bl[p * 2][0] = rl[0]; bl[p * 2][1] = rl[1];
                bl[p * 2 + 1][0] = rl[2]; bl[p * 2 + 1][1] = rl[3];
            }
#pragma unroll
            for (int mt = 0; mt < 4; ++mt)
#pragma unroll
                for (int nt = 0; nt < 4; ++nt) {
                    mma16816(acc[mt][nt], ah[mt], bh[nt]);
                    mma16816(acc[mt][nt], ah[mt], bl[nt]);
                }
        }
    }

    // ------------------------- epilogue -------------------------
    const int r0base = bm + wm * 64;
    const int c0base = bn + wn * 32;
#pragma unroll
    for (int mt = 0; mt < 4; ++mt) {
#pragma unroll
        for (int half = 0; half < 2; ++half) {
            int row = r0base + mt * 16 + (l >> 2) + half * 8;
            if (EPI == 0) {
#pragma unroll
                for (int nt = 0; nt < 4; ++nt) {
                    int col = c0base + nt * 8 + (l & 3) * 2;
                    float v0 = acc[mt][nt][half * 2 + 0] + __ldg(&bias[col]);
                    float v1 = acc[mt][nt][half * 2 + 1] + __ldg(&bias[col + 1]);
                    v0 = 0.5f * v0 * (1.f + erff(v0 * 0.70710678118654752f));
                    v1 = 0.5f * v1 * (1.f + erff(v1 * 0.70710678118654752f));
                    __half2 hp = __floats2half2_rn(v0, v1);
                    size_t o = (size_t)row * DFF + col;
                    *(__half2*)&g_H[o] = hp;
                }
            } else {
                int b = row >> 10;
                int pos = g_selidx[row];
                float gt = g_gate[row];
                size_t o = ((size_t)b * SEQ + pos) * DMODEL;
#pragma unroll
                for (int nt = 0; nt < 4; ++nt) {
                    int col = c0base + nt * 8 + (l & 3) * 2;
                    float2 w;
                    w.x = (acc[mt][nt][half * 2 + 0] + __ldg(&bias[col])) * gt;
                    w.y = (acc[mt][nt][half * 2 + 1] + __ldg(&bias[col + 1])) * gt;
                    *(float2*)&out[o + col] = w;
                }
            }
        }
    }
}

// ------------------------------ launch ------------------------------
extern "C" void kernel_launch(void* const* d_in, const int* in_sizes, int n_in,
                              void* d_out, int out_size) {
    const float* x  = (const float*)d_in[0];
    const float* rw = (const float*)d_in[1];
    const float* rb = (const float*)d_in[2];
    const float* w1 = (const float*)d_in[3];
    const float* b1 = (const float*)d_in[4];
    const float* w2 = (const float*)d_in[5];
    const float* b2 = (const float*)d_in[6];
    float* out = (float*)d_out;

    cudaFuncSetAttribute(hmma_gemm<DMODEL, 0>, cudaFuncAttributeMaxDynamicSharedMemorySize, GEMM_SMEM);
    cudaFuncSetAttribute(hmma_gemm<DFF, 1>,    cudaFuncAttributeMaxDynamicSharedMemorySize, GEMM_SMEM);

    router_kernel<<<(BATCH * SEQ) / 8, 256>>>(x, rw, rb);
    topk_kernel<<<BATCH, 1024>>>();
    gather_convert<<<MROWS, 256>>>(x);
    transpose_split<0><<<dim3(DFF / 32, DMODEL / 32), dim3(32, 8)>>>(w1);
    transpose_split<1><<<dim3(DMODEL / 32, DFF / 32), dim3(32, 8)>>>(w2);

    // GEMM1 + GELU -> H (fp16)
    hmma_gemm<DMODEL, 0><<<dim3(DFF / 128, MROWS / 128), 256, GEMM_SMEM>>>(b1, nullptr);

    zero_kernel<<<(BATCH * SEQ * DMODEL / 4) / 256, 256>>>((float4*)out);

    // GEMM2 + gate + scatter
    hmma_gemm<DFF, 1><<<dim3(DMODEL / 128, MROWS / 128), 256, GEMM_SMEM>>>(b2, out);
}

// round 5
// speedup vs baseline: 5.8404x; 1.8924x over previous
#include <cuda_runtime.h>
#include <cuda_fp16.h>
#include <math.h>
#include <stdint.h>

#define BATCH  4
#define SEQ    4096
#define DMODEL 1024
#define DFF    4096
#define KSEL   1024
#define MROWS  4096

// ------------------------- device scratch (no allocs) -------------------------
__device__ float g_scores[BATCH * SEQ];
__device__ int   g_selidx[MROWS];
__device__ float g_gate[MROWS];
__device__ __half g_A[(size_t)MROWS * DMODEL];   // gathered tokens, fp16
__device__ __half g_H[(size_t)MROWS * DFF];      // GELU(h), fp16
__device__ __half g_W1[(size_t)DFF * DMODEL];    // W1^T  [N][K]
__device__ __half g_W2[(size_t)DMODEL * DFF];    // W2^T  [N][K]

// ------------------------------ helpers ------------------------------
__device__ __forceinline__ uint32_t smem_u32(const void* p) {
    uint32_t a;
    asm("{ .reg .u64 t; cvta.to.shared.u64 t, %1; cvt.u32.u64 %0, t; }"
        : "=r"(a) : "l"(p));
    return a;
}

__device__ __forceinline__ void ldsm4(uint32_t* r, uint32_t addr) {
    asm volatile("ldmatrix.sync.aligned.m8n8.x4.shared.b16 {%0,%1,%2,%3}, [%4];"
                 : "=r"(r[0]), "=r"(r[1]), "=r"(r[2]), "=r"(r[3]) : "r"(addr));
}

__device__ __forceinline__ void mma16816(float* c, const uint32_t* a, const uint32_t* b) {
    asm volatile(
        "mma.sync.aligned.m16n8k16.row.col.f32.f16.f16.f32 "
        "{%0,%1,%2,%3}, {%4,%5,%6,%7}, {%8,%9}, {%0,%1,%2,%3};"
        : "+f"(c[0]), "+f"(c[1]), "+f"(c[2]), "+f"(c[3])
        : "r"(a[0]), "r"(a[1]), "r"(a[2]), "r"(a[3]), "r"(b[0]), "r"(b[1]));
}

__device__ __forceinline__ void cp16(uint32_t dst, const void* src) {
    asm volatile("cp.async.cg.shared.global [%0], [%1], 16;" :: "r"(dst), "l"(src));
}

// swizzled byte offset within a 128-row x 64B tile
__device__ __forceinline__ uint32_t swz(int row, int u) {
    return (uint32_t)(row * 64 + ((u ^ ((row >> 1) & 3)) << 4));
}

// ------------------------------ router ------------------------------
__global__ void router_kernel(const float* __restrict__ x,
                              const float* __restrict__ rw,
                              const float* __restrict__ rb) {
    int warp = (blockIdx.x * blockDim.x + threadIdx.x) >> 5;
    int lane = threadIdx.x & 31;
    if (warp >= BATCH * SEQ) return;
    const float4* xr = (const float4*)(x + (size_t)warp * DMODEL);
    const float4* w4 = (const float4*)rw;
    float acc = 0.f;
#pragma unroll 4
    for (int i = lane; i < DMODEL / 4; i += 32) {
        float4 a = xr[i], w = w4[i];
        acc += a.x * w.x + a.y * w.y + a.z * w.z + a.w * w.w;
    }
#pragma unroll
    for (int o = 16; o; o >>= 1) acc += __shfl_xor_sync(0xffffffffu, acc, o);
    if (lane == 0) g_scores[warp] = acc + rb[0];
}

// ----------------- top-k via 4-level radix select (exact) -----------------
__global__ void topk_select() {
    __shared__ uint32_t skey[SEQ];
    __shared__ int hist[256];
    __shared__ int sK;
    __shared__ uint32_t spfx;
    __shared__ int cntG, cntE;
    const int b = blockIdx.x, tid = threadIdx.x, T = blockDim.x;

    for (int i = tid; i < SEQ; i += T) {
        uint32_t u = __float_as_uint(g_scores[b * SEQ + i]);
        skey[i] = (u & 0x80000000u) ? ~u : (u | 0x80000000u);  // order-preserving
    }
    if (tid == 0) { sK = KSEL; spfx = 0; cntG = 0; cntE = 0; }
    __syncthreads();

    for (int level = 0; level < 4; ++level) {
        const int shift = 24 - level * 8;
        for (int i = tid; i < 256; i += T) hist[i] = 0;
        __syncthreads();
        uint32_t pfx = spfx;
        for (int i = tid; i < SEQ; i += T) {
            uint32_t u = skey[i];
            if (level == 0 || (u >> (shift + 8)) == pfx)
                atomicAdd(&hist[(u >> shift) & 0xFF], 1);
        }
        __syncthreads();
        if (tid == 0) {
            int k = sK, bin = 255;
            for (;; --bin) {
                int c = hist[bin];
                if (k <= c) break;
                k -= c;
            }
            sK = k;
            spfx = (spfx << 8) | (uint32_t)bin;
        }
        __syncthreads();
    }
    const uint32_t thr = spfx;
    const int kE = sK;            // how many ==thr elements to take
    const int G = KSEL - kE;      // count strictly greater
    for (int i = tid; i < SEQ; i += T) {
        uint32_t u = skey[i];
        int slot = -1;
        if (u > thr) slot = atomicAdd(&cntG, 1);
        else if (u == thr) {
            int e = atomicAdd(&cntE, 1);
            if (e < kE) slot = G + e;
        }
        if (slot >= 0) {
            g_selidx[b * KSEL + slot] = i;
            float s = g_scores[b * SEQ + i];
            g_gate[b * KSEL + slot] = 1.f / (1.f + expf(-s));
        }
    }
}

// -------------------- gather selected rows -> fp16 --------------------
__global__ void gather_convert(const float* __restrict__ x) {
    int r = blockIdx.x;
    int b = r >> 10;
    int pos = g_selidx[r];
    const float4* src = (const float4*)(x + ((size_t)b * SEQ + pos) * DMODEL);
    float4 v = src[threadIdx.x];
    __align__(8) __half h[4];
    h[0] = __float2half(v.x); h[1] = __float2half(v.y);
    h[2] = __float2half(v.z); h[3] = __float2half(v.w);
    size_t o = (size_t)r * DMODEL + 4 * threadIdx.x;
    *(uint2*)&g_A[o] = *(uint2*)h;
}

// -------------------- transpose weights -> fp16 [N][K] --------------------
template<int W>
__global__ void transpose_w(const float* __restrict__ src) {
    constexpr int R = (W == 0) ? DMODEL : DFF;    // K of the GEMM
    constexpr int C = (W == 0) ? DFF : DMODEL;    // N of the GEMM
    __half* O = (W == 0) ? g_W1 : g_W2;
    __shared__ float t[32][33];
    int c0 = blockIdx.x * 32, r0 = blockIdx.y * 32;
    int tx = threadIdx.x, ty = threadIdx.y;
#pragma unroll
    for (int j = 0; j < 32; j += 8)
        t[ty + j][tx] = src[(size_t)(r0 + ty + j) * C + c0 + tx];
    __syncthreads();
#pragma unroll
    for (int j = 0; j < 32; j += 8)
        O[(size_t)(c0 + ty + j) * R + r0 + tx] = __float2half(t[tx][ty + j]);
}

// ------------------------------ zero output ------------------------------
__global__ void zero_kernel(float4* __restrict__ out) {
    out[(size_t)blockIdx.x * blockDim.x + threadIdx.x] = make_float4(0.f, 0.f, 0.f, 0.f);
}

// --------------------------- HMMA GEMM (single-pass fp16) ---------------------------
// C[128x128 tile] = A[M,K] * B^T (B stored [N][K]); fp32 accum.
// 8 warps 2(M)x4(N); warp tile 64x32; K-chunk 32; 4-stage cp.async.
// Stage (16KB): A @0, B @8K; rows of 64B, swizzled.
#define STAGES 4
#define STAGE_BYTES 16384
#define GEMM_SMEM (STAGES * STAGE_BYTES)

template<int KDIM, int EPI>
__global__ __launch_bounds__(256, 2)
void hmma_gemm(const float* __restrict__ bias, float* __restrict__ out) {
    extern __shared__ __align__(128) char smem[];
    const int tid = threadIdx.x, l = tid & 31, wid = tid >> 5;
    const int wm = wid >> 2, wn = wid & 3;
    const int bm = blockIdx.y * 128, bn = blockIdx.x * 128;
    const uint32_t sb = smem_u32(smem);
    constexpr int NC = KDIM / 32;

    const __half *A, *B;
    if (EPI == 0) { A = g_A; B = g_W1; }
    else          { A = g_H; B = g_W2; }

    float acc[4][4][4];
#pragma unroll
    for (int i = 0; i < 4; ++i)
#pragma unroll
        for (int j = 0; j < 4; ++j)
#pragma unroll
            for (int k = 0; k < 4; ++k) acc[i][j][k] = 0.f;

    auto load_stage = [&](int ck) {
        uint32_t sbase = sb + (ck & (STAGES - 1)) * STAGE_BYTES;
#pragma unroll
        for (int j = 0; j < 4; ++j) {
            const int sec = j >> 1;           // 0=A, 1=B
            int w = tid + (j & 1) * 256;
            int row = w >> 2, u = w & 3;
            uint32_t dst = sbase + sec * 8192 + swz(row, u);
            const __half* g = sec ? B : A;
            int grow = (sec ? bn : bm) + row;
            cp16(dst, g + (size_t)grow * KDIM + ck * 32 + u * 8);
        }
        asm volatile("cp.async.commit_group;" ::: "memory");
    };

    // prologue
#pragma unroll
    for (int s = 0; s < STAGES - 1; ++s) load_stage(s);

    for (int c = 0; c < NC; ++c) {
        asm volatile("cp.async.wait_group %0;" :: "n"(STAGES - 2) : "memory");
        __syncthreads();
        if (c + STAGES - 1 < NC) load_stage(c + STAGES - 1);
        uint32_t sbase = sb + (c & (STAGES - 1)) * STAGE_BYTES;
#pragma unroll
        for (int s = 0; s < 2; ++s) {
            uint32_t ah[4][4], bh[4][2];
#pragma unroll
            for (int mt = 0; mt < 4; ++mt) {
                int row = wm * 64 + mt * 16 + (l & 15);
                int u = s * 2 + (l >> 4);
                ldsm4(ah[mt], sbase + swz(row, u));
            }
#pragma unroll
            for (int p = 0; p < 2; ++p) {
                int row = wn * 32 + p * 16 + ((l >> 4) << 3) + (l & 7);
                int u = s * 2 + ((l >> 3) & 1);
                uint32_t rh[4];
                ldsm4(rh, sbase + 8192 + swz(row, u));
                bh[p * 2][0] = rh[0]; bh[p * 2][1] = rh[1];
                bh[p * 2 + 1][0] = rh[2]; bh[p * 2 + 1][1] = rh[3];
            }
#pragma unroll
            for (int mt = 0; mt < 4; ++mt)
#pragma unroll
                for (int nt = 0; nt < 4; ++nt)
                    mma16816(acc[mt][nt], ah[mt], bh[nt]);
        }
    }

    // ------------------------- epilogue -------------------------
    const int r0base = bm + wm * 64;
    const int c0base = bn + wn * 32;
#pragma unroll
    for (int mt = 0; mt < 4; ++mt) {
#pragma unroll
        for (int half = 0; half < 2; ++half) {
            int row = r0base + mt * 16 + (l >> 2) + half * 8;
            if (EPI == 0) {
#pragma unroll
                for (int nt = 0; nt < 4; ++nt) {
                    int col = c0base + nt * 8 + (l & 3) * 2;
                    float v0 = acc[mt][nt][half * 2 + 0] + __ldg(&bias[col]);
                    float v1 = acc[mt][nt][half * 2 + 1] + __ldg(&bias[col + 1]);
                    v0 = 0.5f * v0 * (1.f + erff(v0 * 0.70710678118654752f));
                    v1 = 0.5f * v1 * (1.f + erff(v1 * 0.70710678118654752f));
                    *(__half2*)&g_H[(size_t)row * DFF + col] = __floats2half2_rn(v0, v1);
                }
            } else {
                int b = row >> 10;
                int pos = g_selidx[row];
                float gt = g_gate[row];
                size_t o = ((size_t)b * SEQ + pos) * DMODEL;
#pragma unroll
                for (int nt = 0; nt < 4; ++nt) {
                    int col = c0base + nt * 8 + (l & 3) * 2;
                    float2 w;
                    w.x = (acc[mt][nt][half * 2 + 0] + __ldg(&bias[col])) * gt;
                    w.y = (acc[mt][nt][half * 2 + 1] + __ldg(&bias[col + 1])) * gt;
                    *(float2*)&out[o + col] = w;
                }
            }
        }
    }
}

// ------------------------------ launch ------------------------------
extern "C" void kernel_launch(void* const* d_in, const int* in_sizes, int n_in,
                              void* d_out, int out_size) {
    const float* x  = (const float*)d_in[0];
    const float* rw = (const float*)d_in[1];
    const float* rb = (const float*)d_in[2];
    const float* w1 = (const float*)d_in[3];
    const float* b1 = (const float*)d_in[4];
    const float* w2 = (const float*)d_in[5];
    const float* b2 = (const float*)d_in[6];
    float* out = (float*)d_out;

    cudaFuncSetAttribute(hmma_gemm<DMODEL, 0>, cudaFuncAttributeMaxDynamicSharedMemorySize, GEMM_SMEM);
    cudaFuncSetAttribute(hmma_gemm<DFF, 1>,    cudaFuncAttributeMaxDynamicSharedMemorySize, GEMM_SMEM);

    router_kernel<<<(BATCH * SEQ) / 8, 256>>>(x, rw, rb);
    topk_select<<<BATCH, 512>>>();
    gather_convert<<<MROWS, 256>>>(x);
    transpose_w<0><<<dim3(DFF / 32, DMODEL / 32), dim3(32, 8)>>>(w1);
    transpose_w<1><<<dim3(DMODEL / 32, DFF / 32), dim3(32, 8)>>>(w2);

    // GEMM1 + GELU -> H (fp16)
    hmma_gemm<DMODEL, 0><<<dim3(DFF / 128, MROWS / 128), 256, GEMM_SMEM>>>(b1, nullptr);

    zero_kernel<<<(BATCH * SEQ * DMODEL / 4) / 256, 256>>>((float4*)out);

    // GEMM2 + gate + scatter
    hmma_gemm<DFF, 1><<<dim3(DMODEL / 128, MROWS / 128), 256, GEMM_SMEM>>>(b2, out);
}